// round 2
// baseline (speedup 1.0000x reference)
#include <cuda_runtime.h>
#include <cstdint>

// Problem constants (fixed shapes for this problem)
#define CDIM 128      // feature / class dim
#define KPROTO 128    // number of prototypes
#define NMAX (1 << 20)

// Device-global scratch (no allocations allowed)
__device__ double g_sum;
__device__ int    g_cnt;
__device__ float  g_lse[NMAX];
__device__ int    g_list[NMAX];

// ---- packed fp32x2 FMA (Blackwell FFMA2, PTX-only) ----
__device__ __forceinline__ unsigned long long fma2(unsigned long long a,
                                                   unsigned long long b,
                                                   unsigned long long c) {
    unsigned long long d;
    asm("fma.rn.f32x2 %0, %1, %2, %3;" : "=l"(d) : "l"(a), "l"(b), "l"(c));
    return d;
}
__device__ __forceinline__ void unpack2(unsigned long long v, float& lo, float& hi) {
    asm("mov.b64 {%0, %1}, %2;" : "=f"(lo), "=f"(hi) : "l"(v));
}

// ---------------------------------------------------------------------------
__global__ void k_zero() {
    g_sum = 0.0;
    g_cnt = 0;
}

// ---------------------------------------------------------------------------
// Pass 1: per-row logsumexp; finish labeled rows; compact unlabeled rows.
// Block = 256 threads = 8 warps, warp handles 4 rows per tile.
__global__ void k_stats(const float* __restrict__ x,
                        const int* __restrict__ labels,
                        const int* __restrict__ kp,
                        int N) {
    __shared__ int   s_idx[32];
    __shared__ int   s_cnt;
    __shared__ int   s_base;
    __shared__ float s_red[8];

    const int tid  = threadIdx.x;
    const int w    = tid >> 5;
    const int lane = tid & 31;
    const int kk   = kp ? kp[0] : KPROTO;

    float wsum = 0.f;

    for (int tile = blockIdx.x * 32; tile < N; tile += gridDim.x * 32) {
        if (tid == 0) s_cnt = 0;
        __syncthreads();

#pragma unroll
        for (int r = 0; r < 4; r++) {
            int row = tile + w * 4 + r;
            if (row < N) {
                float4 xv = *(const float4*)(x + (size_t)row * CDIM + lane * 4);
                // warp max
                float m = fmaxf(fmaxf(xv.x, xv.y), fmaxf(xv.z, xv.w));
#pragma unroll
                for (int o = 16; o > 0; o >>= 1)
                    m = fmaxf(m, __shfl_xor_sync(0xffffffffu, m, o));
                // warp sum of exp
                float s = __expf(xv.x - m) + __expf(xv.y - m) +
                          __expf(xv.z - m) + __expf(xv.w - m);
#pragma unroll
                for (int o = 16; o > 0; o >>= 1)
                    s += __shfl_xor_sync(0xffffffffu, s, o);
                float lse = m + __logf(s);

                int lab = labels[row];   // uniform across warp
                if (lab < kk) {
                    int comp = lab & 3;
                    float mv = (comp == 0) ? xv.x : (comp == 1) ? xv.y
                              : (comp == 2) ? xv.z : xv.w;
                    float xl = __shfl_sync(0xffffffffu, mv, lab >> 2);
                    if (lane == 0) wsum += lse - xl;
                } else {
                    if (lane == 0) {
                        g_lse[row] = lse;
                        int p = atomicAdd(&s_cnt, 1);
                        s_idx[p] = row;
                    }
                }
            }
        }
        __syncthreads();
        if (tid == 0 && s_cnt > 0) s_base = atomicAdd(&g_cnt, s_cnt);
        __syncthreads();
        if (tid < s_cnt) g_list[s_base + tid] = s_idx[tid];
        __syncthreads();
    }

    if (lane == 0) s_red[w] = wsum;
    __syncthreads();
    if (tid == 0) {
        float t = 0.f;
#pragma unroll
        for (int i = 0; i < 8; i++) t += s_red[i];
        atomicAdd(&g_sum, (double)t);
    }
}

// ---------------------------------------------------------------------------
// Pass 2: for each compacted (unlabeled) row: argmin_j ||x - p_j||, then
// nll = lse - x[jmin]. Prototypes resident in smem (132-float padded rows ->
// conflict-free LDS.128). 8 warps * 4 rows per block tile; 4 protos per lane.
__global__ void __launch_bounds__(256, 2)
k_dot(const float* __restrict__ x, const float* __restrict__ protos) {
    extern __shared__ float sm[];
    float* p_s = sm;                        // [128][132]
    float* p2h = sm + 128 * 132;            // [128]  0.5*||p_j||^2
    float* x_s = p2h + 128;                 // [8][4][128]
    __shared__ float s_red[8];

    const int tid  = threadIdx.x;
    const int w    = tid >> 5;
    const int lane = tid & 31;

    // load prototypes into padded smem
    for (int i = tid; i < 128 * 128; i += 256) {
        int j = i >> 7, c = i & 127;
        p_s[j * 132 + c] = protos[i];
    }
    __syncthreads();
    if (tid < 128) {
        float s = 0.f;
        for (int c = 0; c < 128; c++) {
            float v = p_s[tid * 132 + c];
            s += v * v;
        }
        p2h[tid] = 0.5f * s;
    }
    __syncthreads();

    const int cnt = g_cnt;
    float wsum = 0.f;
    float* myx = x_s + w * 4 * 128;

    for (int base = blockIdx.x * 32; base < cnt; base += gridDim.x * 32) {
        bool  val[4];
        float lses[4];
#pragma unroll
        for (int r = 0; r < 4; r++) {
            int idx = base + w * 4 + r;
            val[r] = (idx < cnt);
            if (val[r]) {
                int row = g_list[idx];
                float4 xv = *(const float4*)(x + (size_t)row * CDIM + lane * 4);
                *(float4*)(myx + r * 128 + lane * 4) = xv;
                lses[r] = g_lse[row];
            }
        }
        __syncwarp();

        unsigned long long acc[4][4];
#pragma unroll
        for (int a = 0; a < 4; a++)
#pragma unroll
            for (int b = 0; b < 4; b++) acc[a][b] = 0ull;

#pragma unroll 4
        for (int c = 0; c < 128; c += 4) {
            ulonglong2 pv[4];
#pragma unroll
            for (int j4 = 0; j4 < 4; j4++)
                pv[j4] = *(const ulonglong2*)(p_s + (lane + 32 * j4) * 132 + c);
#pragma unroll
            for (int r = 0; r < 4; r++) {
                ulonglong2 xv = *(const ulonglong2*)(myx + r * 128 + c);
#pragma unroll
                for (int j4 = 0; j4 < 4; j4++) {
                    acc[j4][r] = fma2(xv.x, pv[j4].x, acc[j4][r]);
                    acc[j4][r] = fma2(xv.y, pv[j4].y, acc[j4][r]);
                }
            }
        }

        float p2v[4];
#pragma unroll
        for (int j4 = 0; j4 < 4; j4++) p2v[j4] = p2h[lane + 32 * j4];

#pragma unroll
        for (int r = 0; r < 4; r++) {
            // per-lane best over its 4 prototypes (ascending j keeps lowest on tie)
            float lo, hi;
            unpack2(acc[0][r], lo, hi);
            float best = p2v[0] - (lo + hi);
            int   bj   = lane;
#pragma unroll
            for (int j4 = 1; j4 < 4; j4++) {
                unpack2(acc[j4][r], lo, hi);
                float sc = p2v[j4] - (lo + hi);
                int   j  = lane + 32 * j4;
                if (sc < best) { best = sc; bj = j; }
            }
            // warp argmin, tie -> lower index (matches jnp.argmin)
#pragma unroll
            for (int o = 16; o > 0; o >>= 1) {
                float ob = __shfl_xor_sync(0xffffffffu, best, o);
                int   oj = __shfl_xor_sync(0xffffffffu, bj, o);
                if (ob < best || (ob == best && oj < bj)) { best = ob; bj = oj; }
            }
            if (val[r] && lane == 0) wsum += lses[r] - myx[r * 128 + bj];
        }
        __syncwarp();   // x_s reuse next iteration
    }

    if (lane == 0) s_red[w] = wsum;
    __syncthreads();
    if (tid == 0) {
        float t = 0.f;
#pragma unroll
        for (int i = 0; i < 8; i++) t += s_red[i];
        atomicAdd(&g_sum, (double)t);
    }
}

// ---------------------------------------------------------------------------
__global__ void k_fin(float* out, int N) {
    out[0] = (float)(g_sum / (double)N);
}

// ---------------------------------------------------------------------------
extern "C" void kernel_launch(void* const* d_in, const int* in_sizes, int n_in,
                              void* d_out, int out_size) {
    const float* x      = (const float*)d_in[0];
    const int*   labels = (const int*)d_in[1];
    const float* protos = (const float*)d_in[2];
    const int*   kp     = (n_in > 3) ? (const int*)d_in[3] : nullptr;
    const int N = in_sizes[1];

    const int smem_dot = (128 * 132 + 128 + 8 * 4 * 128) * (int)sizeof(float);
    cudaFuncSetAttribute(k_dot, cudaFuncAttributeMaxDynamicSharedMemorySize, smem_dot);

    k_zero<<<1, 1>>>();
    k_stats<<<2368, 256>>>(x, labels, kp, N);
    k_dot<<<2368, 256, smem_dot>>>(x, protos);
    k_fin<<<1, 1>>>((float*)d_out, N);
}

// round 6
// speedup vs baseline: 2.4682x; 2.4682x over previous
#include <cuda_runtime.h>
#include <cuda_bf16.h>
#include <cstdint>

#define CDIM   128
#define TILE_M 128
#define XSTRIDE 136   // bf16 elements per smem row (conflict-free ldmatrix)

__device__ double g_sum;

// dynamic smem layout (bytes)
#define SM_XB   0                         // X tile bf16 [128][136] = 34816
#define SM_PB   34816                     // protos bf16 [128][136] = 34816
#define SM_P2   69632                     // 128 f: 0.5*||p_j||^2
#define SM_LSE  70144                     // 128 f: per-row lse
#define SM_RED  70656                     // 8 f
#define SMEM_TOTAL 70720

__device__ __forceinline__ uint32_t smem_u32(const void* p) {
    uint32_t a;
    asm("{ .reg .u64 t; cvta.to.shared.u64 t, %1; cvt.u32.u64 %0, t; }"
        : "=r"(a) : "l"(p));
    return a;
}

__device__ __forceinline__ void ldsm_x4(uint32_t* r, uint32_t addr) {
    asm volatile("ldmatrix.sync.aligned.m8n8.x4.shared.b16 {%0,%1,%2,%3}, [%4];"
                 : "=r"(r[0]), "=r"(r[1]), "=r"(r[2]), "=r"(r[3]) : "r"(addr));
}

__device__ __forceinline__ void mma_bf16(float* d, const uint32_t* a,
                                         uint32_t b0, uint32_t b1) {
    asm volatile(
        "mma.sync.aligned.m16n8k16.row.col.f32.bf16.bf16.f32 "
        "{%0,%1,%2,%3}, {%4,%5,%6,%7}, {%8,%9}, {%0,%1,%2,%3};"
        : "+f"(d[0]), "+f"(d[1]), "+f"(d[2]), "+f"(d[3])
        : "r"(a[0]), "r"(a[1]), "r"(a[2]), "r"(a[3]), "r"(b0), "r"(b1));
}

__global__ void k_zero() { g_sum = 0.0; }

// ---------------------------------------------------------------------------
// Fused: lse + bf16 tensor-core GEMM (x @ P^T) + argmin + NLL + reduce.
// 256 threads = 8 warps. Warp w owns rows [16w, 16w+16) of each 128-row tile.
__global__ void __launch_bounds__(256, 2)
k_main(const float* __restrict__ x,
       const int* __restrict__ labels,
       const float* __restrict__ protos,
       const int* __restrict__ kp,
       int N) {
    extern __shared__ __align__(1024) char sm[];
    const uint32_t smb = smem_u32(sm);
    float* p2s  = (float*)(sm + SM_P2);
    float* lses = (float*)(sm + SM_LSE);
    float* red  = (float*)(sm + SM_RED);

    const int tid  = threadIdx.x;
    const int wid  = tid >> 5;
    const int lane = tid & 31;
    const int kk   = kp ? kp[0] : 128;
    const int ntiles = (N + TILE_M - 1) / TILE_M;

    // ---- load prototypes once: bf16 smem [128][136] + 0.5*||p||^2 ----
#pragma unroll
    for (int i = 0; i < 16; i++) {
        int row = wid * 16 + i;
        float4 pv = *(const float4*)(protos + (size_t)row * CDIM + lane * 4);
        float s = pv.x * pv.x + pv.y * pv.y + pv.z * pv.z + pv.w * pv.w;
#pragma unroll
        for (int o = 16; o > 0; o >>= 1)
            s += __shfl_xor_sync(0xffffffffu, s, o);
        if (lane == 0) p2s[row] = 0.5f * s;
        __nv_bfloat162* dst =
            (__nv_bfloat162*)(sm + SM_PB + (row * XSTRIDE + 4 * lane) * 2);
        dst[0] = __floats2bfloat162_rn(pv.x, pv.y);
        dst[1] = __floats2bfloat162_rn(pv.z, pv.w);
    }
    __syncthreads();

    // precomputed ldmatrix lane addresses
    const uint32_t a_addr_base = smb + SM_XB +
        ((wid * 16 + (lane & 15)) * XSTRIDE + 8 * (lane >> 4)) * 2;
    const uint32_t b_addr_base = smb + SM_PB +
        ((lane & 7) * XSTRIDE + 8 * (lane >> 3)) * 2;

    float acc = 0.f;

    for (int tile = blockIdx.x; tile < ntiles; tile += gridDim.x) {
        const int rbase = tile * TILE_M;

        // ---- phase A: load 16 rows, lse, bf16 -> smem ----
#pragma unroll
        for (int half = 0; half < 2; half++) {
            float4 xr[8];
#pragma unroll
            for (int i = 0; i < 8; i++) {
                int grow = rbase + wid * 16 + half * 8 + i;
                xr[i] = (grow < N)
                      ? *(const float4*)(x + (size_t)grow * CDIM + lane * 4)
                      : make_float4(0.f, 0.f, 0.f, 0.f);
            }
#pragma unroll
            for (int i = 0; i < 8; i++) {
                int row = wid * 16 + half * 8 + i;
                float4 xv = xr[i];
                float m = fmaxf(fmaxf(xv.x, xv.y), fmaxf(xv.z, xv.w));
#pragma unroll
                for (int o = 16; o > 0; o >>= 1)
                    m = fmaxf(m, __shfl_xor_sync(0xffffffffu, m, o));
                float s = __expf(xv.x - m) + __expf(xv.y - m)
                        + __expf(xv.z - m) + __expf(xv.w - m);
#pragma unroll
                for (int o = 16; o > 0; o >>= 1)
                    s += __shfl_xor_sync(0xffffffffu, s, o);
                if (lane == 0) lses[row] = m + __logf(s);
                __nv_bfloat162* dst =
                    (__nv_bfloat162*)(sm + SM_XB + (row * XSTRIDE + 4 * lane) * 2);
                dst[0] = __floats2bfloat162_rn(xv.x, xv.y);
                dst[1] = __floats2bfloat162_rn(xv.z, xv.w);
            }
        }
        __syncthreads();

        // ---- phase B: warp-level GEMM, D[16 rows][128 protos] ----
        float d[16][4];
#pragma unroll
        for (int nf = 0; nf < 16; nf++) {
            d[nf][0] = 0.f; d[nf][1] = 0.f; d[nf][2] = 0.f; d[nf][3] = 0.f;
        }

#pragma unroll
        for (int ks2 = 0; ks2 < 4; ks2++) {
            // A for k-steps 2*ks2 and 2*ks2+1 (16 cols each)
            uint32_t a0[4], a1[4];
            ldsm_x4(a0, a_addr_base + (32 * ks2) * 2);
            ldsm_x4(a1, a_addr_base + (32 * ks2 + 16) * 2);
#pragma unroll
            for (int nf = 0; nf < 16; nf++) {
                uint32_t b[4];
                ldsm_x4(b, b_addr_base + (8 * nf * XSTRIDE + 32 * ks2) * 2);
                mma_bf16(d[nf], a0, b[0], b[1]);
                mma_bf16(d[nf], a1, b[2], b[3]);
            }
        }

        // ---- phase C: argmax(dot - 0.5||p||^2) == argmin dist ----
        // lane quad q = lane>>2 owns rows r0 = 16*wid+q, r1 = r0+8.
        float best0 = -3.4e38f, best1 = -3.4e38f;
        int   bj0 = 0, bj1 = 0;
#pragma unroll
        for (int nf = 0; nf < 16; nf++) {
            int jb = 8 * nf + 2 * (lane & 3);
            float p2a = p2s[jb], p2b = p2s[jb + 1];
            float s00 = d[nf][0] - p2a, s01 = d[nf][1] - p2b;
            float s10 = d[nf][2] - p2a, s11 = d[nf][3] - p2b;
            if (s00 > best0) { best0 = s00; bj0 = jb; }
            if (s01 > best0) { best0 = s01; bj0 = jb + 1; }
            if (s10 > best1) { best1 = s10; bj1 = jb; }
            if (s11 > best1) { best1 = s11; bj1 = jb + 1; }
        }
#pragma unroll
        for (int o = 1; o < 4; o <<= 1) {
            float ob = __shfl_xor_sync(0xffffffffu, best0, o);
            int   oj = __shfl_xor_sync(0xffffffffu, bj0, o);
            if (ob > best0 || (ob == best0 && oj < bj0)) { best0 = ob; bj0 = oj; }
            ob = __shfl_xor_sync(0xffffffffu, best1, o);
            oj = __shfl_xor_sync(0xffffffffu, bj1, o);
            if (ob > best1 || (ob == best1 && oj < bj1)) { best1 = ob; bj1 = oj; }
        }

        if ((lane & 3) == 0) {
            int q  = lane >> 2;
            int r0 = wid * 16 + q;
            int r1 = r0 + 8;
            int g0 = rbase + r0, g1 = rbase + r1;
            if (g0 < N) {
                int lab = labels[g0];
                int je  = (lab < kk) ? lab : bj0;
                acc += lses[r0] - __ldg(x + (size_t)g0 * CDIM + je);
            }
            if (g1 < N) {
                int lab = labels[g1];
                int je  = (lab < kk) ? lab : bj1;
                acc += lses[r1] - __ldg(x + (size_t)g1 * CDIM + je);
            }
        }
        __syncthreads();   // protect XB reuse next tile
    }

    // ---- block reduce ----
#pragma unroll
    for (int o = 16; o > 0; o >>= 1)
        acc += __shfl_xor_sync(0xffffffffu, acc, o);
    if (lane == 0) red[wid] = acc;
    __syncthreads();
    if (tid == 0) {
        float t = 0.f;
#pragma unroll
        for (int i = 0; i < 8; i++) t += red[i];
        atomicAdd(&g_sum, (double)t);
    }
}

// ---------------------------------------------------------------------------
__global__ void k_fin(float* out, int N) {
    out[0] = (float)(g_sum / (double)N);
}

// ---------------------------------------------------------------------------
extern "C" void kernel_launch(void* const* d_in, const int* in_sizes, int n_in,
                              void* d_out, int out_size) {
    const float* x      = (const float*)d_in[0];
    const int*   labels = (const int*)d_in[1];
    const float* protos = (const float*)d_in[2];
    const int*   kp     = (n_in > 3) ? (const int*)d_in[3] : nullptr;
    const int N = in_sizes[1];

    cudaFuncSetAttribute(k_main, cudaFuncAttributeMaxDynamicSharedMemorySize,
                         SMEM_TOTAL);

    k_zero<<<1, 1>>>();
    k_main<<<296, 256, SMEM_TOTAL>>>(x, labels, protos, kp, N);
    k_fin<<<1, 1>>>((float*)d_out, N);
}